// round 9
// baseline (speedup 1.0000x reference)
#include <cuda_runtime.h>
#include <cstdint>

#define D 96
#define MAXN 100000
#define MAXE 800000

// ---------------- device scratch (no allocation allowed) ----------------
__device__ int   g_deg[MAXN];
__device__ int   g_start[MAXN];
__device__ int   g_cursor[MAXN];
__device__ int   g_total;
__device__ int   g_dsts[MAXE];      // dst permuted into CSR slabs
__device__ float g_hg[MAXN * D];    // GEMM output (both layers)
__device__ float g_ha[MAXN * D];    // layer-1 aggregation output
__device__ float g_p[MAXN];
__device__ float g_q[MAXN];

// packed f32x2 helpers (Blackwell FFMA2 — ptxas never auto-fuses this)
#define FMA_F32X2(acc, a, b) \
    asm("fma.rn.f32x2 %0, %1, %2, %0;" : "+l"(acc) : "l"(a), "l"(b))
#define BCAST_F32X2(out, v) \
    asm("mov.b64 %0, {%1, %1};" : "=l"(out) : "r"(v))
#define UNPACK_F32X2(lo, hi, in) \
    asm("mov.b64 {%0, %1}, %2;" : "=r"(lo), "=r"(hi) : "l"(in))

// ---------------- zero degrees + allocator -------------------------------
__global__ void k_zero(int n) {
    int i = blockIdx.x * blockDim.x + threadIdx.x;
    if (i < n) g_deg[i] = 0;
    if (i == 0) g_total = 0;
}

// ---------------- degree count (src read straight from edge_index) ------
__global__ void k_convert(const void* __restrict__ ei, int E) {
    int i = blockIdx.x * blockDim.x + threadIdx.x;
    const int* p32 = (const int*)ei;
    // first N src entries are arange(N): int64 layout => 32-bit word 3 == 0
    bool is64 = (p32[3] == 0);
    if (i < E) {
        int s;
        if (is64) {
            const long long* p64 = (const long long*)ei;
            s = (int)p64[i];
        } else {
            s = p32[i];
        }
        atomicAdd(&g_deg[s], 1);
    }
}

// Warp-aggregated slab allocation: warp-local inclusive scan of deg, ONE
// atomicAdd per warp to the global counter.
__global__ void k_alloc(int n) {
    int i = blockIdx.x * blockDim.x + threadIdx.x;
    int lane = threadIdx.x & 31;
    int d = (i < n) ? g_deg[i] : 0;
    int x = d;
    #pragma unroll
    for (int o = 1; o < 32; o <<= 1) {
        int t = __shfl_up_sync(0xffffffffu, x, o);
        if (lane >= o) x += t;
    }
    int warptot = __shfl_sync(0xffffffffu, x, 31);
    int base = 0;
    if (lane == 0) base = atomicAdd(&g_total, warptot);
    base = __shfl_sync(0xffffffffu, base, 0);
    if (i < n) {
        int s = base + x - d;   // exclusive within warp
        g_start[i] = s;
        g_cursor[i] = s;
    }
}

// permute dst into per-src slabs; src re-read directly from edge_index
__global__ void k_scatter(const void* __restrict__ ei, int E) {
    int i = blockIdx.x * blockDim.x + threadIdx.x;
    const int* p32 = (const int*)ei;
    bool is64 = (p32[3] == 0);
    if (i < E) {
        int s, d;
        if (is64) {
            const long long* p64 = (const long long*)ei;
            s = (int)p64[i];
            d = (int)p64[E + i];
        } else {
            s = p32[i];
            d = p32[E + i];
        }
        int pos = atomicAdd(&g_cursor[s], 1);
        g_dsts[pos] = d;
    }
}

// ---------------- GEMM: C[n,96] = A[n,96] @ W[96,96] + fused p/q ---------
// tile M=128, full N=96, K chunked by 32. 256 threads = 16x16, thread owns
// rows ty*8..ty*8+7 x cols tx*6..tx*6+5. Accumulators are f32x2 pairs along
// ROWS: Xs is stored transposed [k][row] so row-pairs load as LDS.64/128,
// and Ws2 holds pre-duplicated (w,w) pairs, so the 32-step k-loop is
// 24 FFMA2 + 5 LDS.128 per step with zero packing movs.
__global__ __launch_bounds__(256) void k_gemm(const float* __restrict__ Aext,
                                              int useExt,
                                              const float* __restrict__ W,
                                              const float* __restrict__ av,
                                              int n) {
    __shared__ float Xs[32 * 132];                    // [k][row], pad 132
    __shared__ unsigned long long Ws2[32 * 96];       // [k][col] dup pairs
    const float* A = useExt ? Aext : g_ha;

    int tx = threadIdx.x & 15;
    int ty = threadIdx.x >> 4;
    int rowBase = blockIdx.x * 128;

    // acc2[rp][c]: lo = row ty*8+2rp, hi = row ty*8+2rp+1, col tx*6+c
    unsigned long long acc2[4][6];
    #pragma unroll
    for (int rp = 0; rp < 4; rp++)
        #pragma unroll
        for (int c = 0; c < 6; c++) acc2[rp][c] = 0ull;

    for (int kc = 0; kc < 3; kc++) {
        // A chunk: 128 rows x 32 k, stored transposed Xs[k][row]
        for (int idx = threadIdx.x; idx < 128 * 8; idx += 256) {
            int r = idx >> 3, c4 = idx & 7;
            int gr = rowBase + r;
            float4 v = make_float4(0.f, 0.f, 0.f, 0.f);
            if (gr < n) v = *(const float4*)(A + gr * 96 + kc * 32 + c4 * 4);
            Xs[(c4 * 4 + 0) * 132 + r] = v.x;
            Xs[(c4 * 4 + 1) * 132 + r] = v.y;
            Xs[(c4 * 4 + 2) * 132 + r] = v.z;
            Xs[(c4 * 4 + 3) * 132 + r] = v.w;
        }
        // W chunk: 32 k x 96 cols, duplicated into f32x2 pairs
        for (int idx = threadIdx.x; idx < 32 * 24; idx += 256) {
            int r = idx / 24, c4 = idx - r * 24;
            float4 w = *(const float4*)(W + (kc * 32 + r) * 96 + c4 * 4);
            unsigned long long p0, p1, p2, p3;
            BCAST_F32X2(p0, __float_as_uint(w.x));
            BCAST_F32X2(p1, __float_as_uint(w.y));
            BCAST_F32X2(p2, __float_as_uint(w.z));
            BCAST_F32X2(p3, __float_as_uint(w.w));
            Ws2[r * 96 + c4 * 4 + 0] = p0;
            Ws2[r * 96 + c4 * 4 + 1] = p1;
            Ws2[r * 96 + c4 * 4 + 2] = p2;
            Ws2[r * 96 + c4 * 4 + 3] = p3;
        }
        __syncthreads();
        #pragma unroll 4
        for (int k = 0; k < 32; k++) {
            // x row-pairs: 2 LDS.128 = 4 packed pairs (16B aligned)
            ulonglong2 xA = *(const ulonglong2*)(Xs + k * 132 + ty * 8);
            ulonglong2 xB = *(const ulonglong2*)(Xs + k * 132 + ty * 8 + 4);
            unsigned long long xv[4] = {xA.x, xA.y, xB.x, xB.y};
            // w dup-pairs: 3 LDS.128 (16B aligned: tx*6*8B = tx*48)
            const ulonglong2* wp = (const ulonglong2*)(Ws2 + k * 96 + tx * 6);
            ulonglong2 w01 = wp[0], w23 = wp[1], w45 = wp[2];
            unsigned long long wv[6] = {w01.x, w01.y, w23.x, w23.y, w45.x, w45.y};
            #pragma unroll
            for (int rp = 0; rp < 4; rp++)
                #pragma unroll
                for (int c = 0; c < 6; c++)
                    FMA_F32X2(acc2[rp][c], xv[rp], wv[c]);
        }
        __syncthreads();
    }

    // unpack to per-row accumulators, store h, fused p/q epilogue
    float ap[6], aq[6];
    #pragma unroll
    for (int c = 0; c < 6; c++) {
        ap[c] = av[tx * 6 + c];
        aq[c] = av[96 + tx * 6 + c];
    }
    #pragma unroll
    for (int rp = 0; rp < 4; rp++) {
        float accLo[6], accHi[6];
        #pragma unroll
        for (int c = 0; c < 6; c++) {
            uint32_t lo, hi;
            UNPACK_F32X2(lo, hi, acc2[rp][c]);
            accLo[c] = __uint_as_float(lo);
            accHi[c] = __uint_as_float(hi);
        }
        #pragma unroll
        for (int half = 0; half < 2; half++) {
            float* acc = half ? accHi : accLo;
            int gr = rowBase + ty * 8 + rp * 2 + half;
            float pl = 0.f, ql = 0.f;
            #pragma unroll
            for (int c = 0; c < 6; c++) {
                pl += acc[c] * ap[c];
                ql += acc[c] * aq[c];
            }
            #pragma unroll
            for (int o = 8; o; o >>= 1) {
                pl += __shfl_xor_sync(0xffffffffu, pl, o);
                ql += __shfl_xor_sync(0xffffffffu, ql, o);
            }
            if (gr < n) {
                #pragma unroll
                for (int c = 0; c < 6; c++)
                    g_hg[gr * 96 + tx * 6 + c] = acc[c];
                if (tx == 0) { g_p[gr] = pl; g_q[gr] = ql; }
            }
        }
    }
}

// ---------------- warp-per-node aggregation with fused edge weights ------
__global__ void k_agg(float* __restrict__ outExt, int useExt, int relu, int n) {
    int w = (blockIdx.x * blockDim.x + threadIdx.x) >> 5;
    int lane = threadIdx.x & 31;
    if (w >= n) return;
    float* out = useExt ? outExt : g_ha;
    int s = g_start[w];
    int e0 = s + g_deg[w];
    float pw = g_p[w];
    float a0 = 0.f, a1 = 0.f, a2 = 0.f, sep = 0.f;

    for (int base = s; base < e0; base += 32) {
        int j = base + lane;
        int v = 0;
        float wt = 0.f;
        if (j < e0) {
            v = g_dsts[j];
            float sc = pw + g_q[v];
            float l = sc > 0.f ? sc : 0.01f * sc;
            wt = expf(-l);
        }
        sep += wt;
        int m = min(32, e0 - base);
        #pragma unroll 2
        for (int t = 0; t < m; t++) {
            float w_t = __shfl_sync(0xffffffffu, wt, t);
            int   v_t = __shfl_sync(0xffffffffu, v, t);
            const float* hr = g_hg + v_t * 96;
            a0 += w_t * hr[lane];
            a1 += w_t * hr[lane + 32];
            a2 += w_t * hr[lane + 64];
        }
    }
    #pragma unroll
    for (int o = 16; o; o >>= 1)
        sep += __shfl_xor_sync(0xffffffffu, sep, o);

    float inv = 1.0f / sep;
    a0 *= inv; a1 *= inv; a2 *= inv;
    if (relu) {
        a0 = fmaxf(a0, 0.f);
        a1 = fmaxf(a1, 0.f);
        a2 = fmaxf(a2, 0.f);
    }
    out[w * 96 + lane]      = a0;
    out[w * 96 + lane + 32] = a1;
    out[w * 96 + lane + 64] = a2;
}

// ---------------- launch -------------------------------------------------
// Structure build (deg/alloc/scatter) is independent of the layer-1 GEMM;
// fork it onto a side stream so the captured graph runs both concurrently.
extern "C" void kernel_launch(void* const* d_in, const int* in_sizes, int n_in,
                              void* d_out, int out_size) {
    const void*  ei = d_in[0];
    const float* x  = (const float*)d_in[1];
    const float* W1 = (const float*)d_in[2];
    const float* a1 = (const float*)d_in[3];
    const float* W2 = (const float*)d_in[4];
    const float* a2 = (const float*)d_in[5];
    float* out = (float*)d_out;

    int E = in_sizes[0] / 2;
    int n = in_sizes[1] / D;

    int eb = (E + 255) / 256;
    int nb = (n + 255) / 256;
    int gemmb = (n + 127) / 128;
    int warpb = (n * 32 + 255) / 256;

    static cudaStream_t s2 = nullptr;
    static cudaEvent_t evFork = nullptr, evJoin = nullptr;
    if (s2 == nullptr) {
        cudaStreamCreateWithFlags(&s2, cudaStreamNonBlocking);
        cudaEventCreateWithFlags(&evFork, cudaEventDisableTiming);
        cudaEventCreateWithFlags(&evJoin, cudaEventDisableTiming);
    }

    // fork: structure chain on s2
    cudaEventRecord(evFork, 0);
    cudaStreamWaitEvent(s2, evFork, 0);
    k_zero<<<nb, 256, 0, s2>>>(n);
    k_convert<<<eb, 256, 0, s2>>>(ei, E);
    k_alloc<<<nb, 256, 0, s2>>>(n);
    k_scatter<<<eb, 256, 0, s2>>>(ei, E);
    cudaEventRecord(evJoin, s2);

    // main stream: layer-1 GEMM runs concurrently with structure build
    k_gemm<<<gemmb, 256>>>(x, 1, W1, a1, n);

    // join, then the dependent chain
    cudaStreamWaitEvent(0, evJoin, 0);
    k_agg<<<warpb, 256>>>(out, 0, 0, n);             // -> g_ha
    k_gemm<<<gemmb, 256>>>(nullptr, 0, W2, a2, n);   // g_ha @ W2 -> g_hg
    k_agg<<<warpb, 256>>>(out, 1, 1, n);             // -> d_out with ReLU
}

// round 11
// speedup vs baseline: 1.7088x; 1.7088x over previous
#include <cuda_runtime.h>
#include <cstdint>

#define D 96
#define MAXN 100000
#define MAXE 800000

// ---------------- device scratch (no allocation allowed) ----------------
__device__ int   g_deg[MAXN];
__device__ int   g_start[MAXN];
__device__ int   g_cursor[MAXN];
__device__ int   g_total;
__device__ int   g_dsts[MAXE];      // dst permuted into CSR slabs
__device__ float g_hg[MAXN * D];    // GEMM output (both layers)
__device__ float g_ha[MAXN * D];    // layer-1 aggregation output
__device__ float g_p[MAXN];
__device__ float g_q[MAXN];

// packed f32x2 helpers (Blackwell FFMA2 — ptxas never auto-fuses this)
#define FMA_F32X2(acc, a, b) \
    asm("fma.rn.f32x2 %0, %1, %2, %0;" : "+l"(acc) : "l"(a), "l"(b))
#define BCAST_F32X2(out, v) \
    asm("mov.b64 %0, {%1, %1};" : "=l"(out) : "r"(v))
#define UNPACK_F32X2(lo, hi, in) \
    asm("mov.b64 {%0, %1}, %2;" : "=r"(lo), "=r"(hi) : "l"(in))

// ---------------- degree count (src read straight from edge_index) ------
__global__ void k_convert(const void* __restrict__ ei, int E) {
    int i = blockIdx.x * blockDim.x + threadIdx.x;
    const int* p32 = (const int*)ei;
    // first N src entries are arange(N): int64 layout => 32-bit word 3 == 0
    bool is64 = (p32[3] == 0);
    if (i < E) {
        int s;
        if (is64) {
            const long long* p64 = (const long long*)ei;
            s = (int)p64[i];
        } else {
            s = p32[i];
        }
        atomicAdd(&g_deg[s], 1);
    }
}

// Warp-aggregated slab allocation: warp-local inclusive scan of deg, ONE
// atomicAdd per warp to the global counter.
__global__ void k_alloc(int n) {
    int i = blockIdx.x * blockDim.x + threadIdx.x;
    int lane = threadIdx.x & 31;
    int d = (i < n) ? g_deg[i] : 0;
    int x = d;
    #pragma unroll
    for (int o = 1; o < 32; o <<= 1) {
        int t = __shfl_up_sync(0xffffffffu, x, o);
        if (lane >= o) x += t;
    }
    int warptot = __shfl_sync(0xffffffffu, x, 31);
    int base = 0;
    if (lane == 0) base = atomicAdd(&g_total, warptot);
    base = __shfl_sync(0xffffffffu, base, 0);
    if (i < n) {
        int s = base + x - d;   // exclusive within warp
        g_start[i] = s;
        g_cursor[i] = s;
    }
}

// permute dst into per-src slabs; src re-read directly from edge_index
__global__ void k_scatter(const void* __restrict__ ei, int E) {
    int i = blockIdx.x * blockDim.x + threadIdx.x;
    const int* p32 = (const int*)ei;
    bool is64 = (p32[3] == 0);
    if (i < E) {
        int s, d;
        if (is64) {
            const long long* p64 = (const long long*)ei;
            s = (int)p64[i];
            d = (int)p64[E + i];
        } else {
            s = p32[i];
            d = p32[E + i];
        }
        int pos = atomicAdd(&g_cursor[s], 1);
        g_dsts[pos] = d;
    }
}

// ---------------- GEMM: C[n,96] = A[n,96] @ W[96,96] + fused p/q ---------
// (reverted to the R6 version — measured fastest)
// tile M=128, full N=96, K chunked by 32. 256 threads = 16x16, each thread
// computes an 8x6 microtile held as 8x3 packed f32x2 accumulators driven by
// fma.rn.f32x2 (2x fp32 FMA throughput, bit-exact). Epilogue computes
// p=h.a[:96], q=h.a[96:] by shfl reduction over the 16 tx lanes.
__global__ __launch_bounds__(256) void k_gemm(const float* __restrict__ Aext,
                                              int useExt,
                                              const float* __restrict__ W,
                                              const float* __restrict__ av,
                                              int n) {
    __shared__ float Xs[128 * 33];
    __shared__ float Ws[32 * 96];
    const float* A = useExt ? Aext : g_ha;

    int tx = threadIdx.x & 15;
    int ty = threadIdx.x >> 4;
    int rowBase = blockIdx.x * 128;

    unsigned long long acc2[8][3];
    #pragma unroll
    for (int r = 0; r < 8; r++)
        #pragma unroll
        for (int j = 0; j < 3; j++) acc2[r][j] = 0ull;

    for (int kc = 0; kc < 3; kc++) {
        for (int idx = threadIdx.x; idx < 128 * 8; idx += 256) {
            int r = idx >> 3, c4 = idx & 7;
            int gr = rowBase + r;
            float4 v = make_float4(0.f, 0.f, 0.f, 0.f);
            if (gr < n) v = *(const float4*)(A + gr * 96 + kc * 32 + c4 * 4);
            Xs[r * 33 + c4 * 4 + 0] = v.x;
            Xs[r * 33 + c4 * 4 + 1] = v.y;
            Xs[r * 33 + c4 * 4 + 2] = v.z;
            Xs[r * 33 + c4 * 4 + 3] = v.w;
        }
        for (int idx = threadIdx.x; idx < 32 * 24; idx += 256) {
            int r = idx / 24, c4 = idx - r * 24;
            *(float4*)(Ws + r * 96 + c4 * 4) =
                *(const float4*)(W + (kc * 32 + r) * 96 + c4 * 4);
        }
        __syncthreads();
        #pragma unroll 8
        for (int k = 0; k < 32; k++) {
            unsigned long long wv[3];
            const unsigned long long* wp =
                (const unsigned long long*)(Ws + k * 96 + tx * 6);
            wv[0] = wp[0]; wv[1] = wp[1]; wv[2] = wp[2];
            #pragma unroll
            for (int r = 0; r < 8; r++) {
                uint32_t xu = __float_as_uint(Xs[(ty * 8 + r) * 33 + k]);
                unsigned long long xx;
                BCAST_F32X2(xx, xu);
                FMA_F32X2(acc2[r][0], xx, wv[0]);
                FMA_F32X2(acc2[r][1], xx, wv[1]);
                FMA_F32X2(acc2[r][2], xx, wv[2]);
            }
        }
        __syncthreads();
    }

    float ap[6], aq[6];
    #pragma unroll
    for (int c = 0; c < 6; c++) {
        ap[c] = av[tx * 6 + c];
        aq[c] = av[96 + tx * 6 + c];
    }
    #pragma unroll
    for (int r = 0; r < 8; r++) {
        float acc[6];
        #pragma unroll
        for (int j = 0; j < 3; j++) {
            uint32_t lo, hi;
            UNPACK_F32X2(lo, hi, acc2[r][j]);
            acc[j * 2]     = __uint_as_float(lo);
            acc[j * 2 + 1] = __uint_as_float(hi);
        }
        int gr = rowBase + ty * 8 + r;
        float pl = 0.f, ql = 0.f;
        #pragma unroll
        for (int c = 0; c < 6; c++) {
            pl += acc[c] * ap[c];
            ql += acc[c] * aq[c];
        }
        #pragma unroll
        for (int o = 8; o; o >>= 1) {
            pl += __shfl_xor_sync(0xffffffffu, pl, o);
            ql += __shfl_xor_sync(0xffffffffu, ql, o);
        }
        if (gr < n) {
            #pragma unroll
            for (int c = 0; c < 6; c++)
                g_hg[gr * 96 + tx * 6 + c] = acc[c];
            if (tx == 0) { g_p[gr] = pl; g_q[gr] = ql; }
        }
    }
}

// ---------------- warp-per-node aggregation with fused edge weights ------
// avg degree = E/N = 8, so the deg<=32 single-chunk fast path is the common
// case: one weight computation, one broadcast loop, no chunk bookkeeping.
__global__ void k_agg(float* __restrict__ outExt, int useExt, int relu, int n) {
    int w = (blockIdx.x * blockDim.x + threadIdx.x) >> 5;
    int lane = threadIdx.x & 31;
    if (w >= n) return;
    float* out = useExt ? outExt : g_ha;
    int s = g_start[w];
    int deg = g_deg[w];
    float pw = g_p[w];
    float a0 = 0.f, a1 = 0.f, a2 = 0.f, sep = 0.f;

    if (deg <= 32) {
        int v = 0;
        float wt = 0.f;
        if (lane < deg) {
            v = __ldg(&g_dsts[s + lane]);
            float sc = pw + __ldg(&g_q[v]);
            float l = sc > 0.f ? sc : 0.01f * sc;
            wt = expf(-l);
        }
        sep = wt;
        for (int t = 0; t < deg; t++) {
            float w_t = __shfl_sync(0xffffffffu, wt, t);
            int   v_t = __shfl_sync(0xffffffffu, v, t);
            const float* hr = g_hg + v_t * 96;
            a0 += w_t * __ldg(hr + lane);
            a1 += w_t * __ldg(hr + lane + 32);
            a2 += w_t * __ldg(hr + lane + 64);
        }
    } else {
        int e0 = s + deg;
        for (int base = s; base < e0; base += 32) {
            int j = base + lane;
            int v = 0;
            float wt = 0.f;
            if (j < e0) {
                v = __ldg(&g_dsts[j]);
                float sc = pw + __ldg(&g_q[v]);
                float l = sc > 0.f ? sc : 0.01f * sc;
                wt = expf(-l);
            }
            sep += wt;
            int m = min(32, e0 - base);
            #pragma unroll 2
            for (int t = 0; t < m; t++) {
                float w_t = __shfl_sync(0xffffffffu, wt, t);
                int   v_t = __shfl_sync(0xffffffffu, v, t);
                const float* hr = g_hg + v_t * 96;
                a0 += w_t * __ldg(hr + lane);
                a1 += w_t * __ldg(hr + lane + 32);
                a2 += w_t * __ldg(hr + lane + 64);
            }
        }
    }
    #pragma unroll
    for (int o = 16; o; o >>= 1)
        sep += __shfl_xor_sync(0xffffffffu, sep, o);

    float inv = 1.0f / sep;
    a0 *= inv; a1 *= inv; a2 *= inv;
    if (relu) {
        a0 = fmaxf(a0, 0.f);
        a1 = fmaxf(a1, 0.f);
        a2 = fmaxf(a2, 0.f);
    }
    out[w * 96 + lane]      = a0;
    out[w * 96 + lane + 32] = a1;
    out[w * 96 + lane + 64] = a2;
}

// ---------------- launch -------------------------------------------------
// Structure build (deg/alloc/scatter) is independent of the layer-1 GEMM;
// fork it onto a side stream so the captured graph runs both concurrently.
extern "C" void kernel_launch(void* const* d_in, const int* in_sizes, int n_in,
                              void* d_out, int out_size) {
    const void*  ei = d_in[0];
    const float* x  = (const float*)d_in[1];
    const float* W1 = (const float*)d_in[2];
    const float* a1 = (const float*)d_in[3];
    const float* W2 = (const float*)d_in[4];
    const float* a2 = (const float*)d_in[5];
    float* out = (float*)d_out;

    int E = in_sizes[0] / 2;
    int n = in_sizes[1] / D;

    int eb = (E + 255) / 256;
    int nb = (n + 255) / 256;
    int gemmb = (n + 127) / 128;
    int warpb = (n * 32 + 255) / 256;

    static cudaStream_t s2 = nullptr;
    static cudaEvent_t evFork = nullptr, evJoin = nullptr;
    static int* p_deg = nullptr;
    static int* p_total = nullptr;
    if (s2 == nullptr) {
        cudaStreamCreateWithFlags(&s2, cudaStreamNonBlocking);
        cudaEventCreateWithFlags(&evFork, cudaEventDisableTiming);
        cudaEventCreateWithFlags(&evJoin, cudaEventDisableTiming);
        cudaGetSymbolAddress((void**)&p_deg, g_deg);
        cudaGetSymbolAddress((void**)&p_total, g_total);
    }

    // fork: structure chain on s2 (memset replaces the k_zero kernel)
    cudaEventRecord(evFork, 0);
    cudaStreamWaitEvent(s2, evFork, 0);
    cudaMemsetAsync(p_deg, 0, n * sizeof(int), s2);
    cudaMemsetAsync(p_total, 0, sizeof(int), s2);
    k_convert<<<eb, 256, 0, s2>>>(ei, E);
    k_alloc<<<nb, 256, 0, s2>>>(n);
    k_scatter<<<eb, 256, 0, s2>>>(ei, E);
    cudaEventRecord(evJoin, s2);

    // main stream: layer-1 GEMM runs concurrently with structure build
    k_gemm<<<gemmb, 256>>>(x, 1, W1, a1, n);

    // join, then the dependent chain
    cudaStreamWaitEvent(0, evJoin, 0);
    k_agg<<<warpb, 256>>>(out, 0, 0, n);             // -> g_ha
    k_gemm<<<gemmb, 256>>>(nullptr, 0, W2, a2, n);   // g_ha @ W2 -> g_hg
    k_agg<<<warpb, 256>>>(out, 1, 1, n);             // -> d_out with ReLU
}

// round 14
// speedup vs baseline: 1.7370x; 1.0165x over previous
#include <cuda_runtime.h>
#include <cstdint>

#define D 96
#define MAXN 100000
#define MAXE 800000

// ---------------- device scratch (no allocation allowed) ----------------
__device__ int   g_deg[MAXN];
__device__ int   g_start[MAXN];
__device__ int   g_cursor[MAXN];
__device__ int   g_total;
__device__ int   g_dsts[MAXE];      // dst permuted into CSR slabs
__device__ float g_hg[MAXN * D];    // GEMM output (both layers)
__device__ float g_ha[MAXN * D];    // layer-1 aggregation output
__device__ float g_p[MAXN];
__device__ float g_q[MAXN];

// packed f32x2 helpers (Blackwell FFMA2 — ptxas never auto-fuses this)
#define FMA_F32X2(acc, a, b) \
    asm("fma.rn.f32x2 %0, %1, %2, %0;" : "+l"(acc) : "l"(a), "l"(b))
#define BCAST_F32X2(out, v) \
    asm("mov.b64 %0, {%1, %1};" : "=l"(out) : "r"(v))
#define UNPACK_F32X2(lo, hi, in) \
    asm("mov.b64 {%0, %1}, %2;" : "=r"(lo), "=r"(hi) : "l"(in))

// ---------------- degree count (src read straight from edge_index) ------
__global__ void k_convert(const void* __restrict__ ei, int E) {
    int i = blockIdx.x * blockDim.x + threadIdx.x;
    const int* p32 = (const int*)ei;
    // first N src entries are arange(N): int64 layout => 32-bit word 3 == 0
    bool is64 = (p32[3] == 0);
    if (i < E) {
        int s;
        if (is64) {
            const long long* p64 = (const long long*)ei;
            s = (int)p64[i];
        } else {
            s = p32[i];
        }
        atomicAdd(&g_deg[s], 1);
    }
}

// Warp-aggregated slab allocation: warp-local inclusive scan of deg, ONE
// atomicAdd per warp to the global counter.
__global__ void k_alloc(int n) {
    int i = blockIdx.x * blockDim.x + threadIdx.x;
    int lane = threadIdx.x & 31;
    int d = (i < n) ? g_deg[i] : 0;
    int x = d;
    #pragma unroll
    for (int o = 1; o < 32; o <<= 1) {
        int t = __shfl_up_sync(0xffffffffu, x, o);
        if (lane >= o) x += t;
    }
    int warptot = __shfl_sync(0xffffffffu, x, 31);
    int base = 0;
    if (lane == 0) base = atomicAdd(&g_total, warptot);
    base = __shfl_sync(0xffffffffu, base, 0);
    if (i < n) {
        int s = base + x - d;   // exclusive within warp
        g_start[i] = s;
        g_cursor[i] = s;
    }
}

// permute dst into per-src slabs; src re-read directly from edge_index
__global__ void k_scatter(const void* __restrict__ ei, int E) {
    int i = blockIdx.x * blockDim.x + threadIdx.x;
    const int* p32 = (const int*)ei;
    bool is64 = (p32[3] == 0);
    if (i < E) {
        int s, d;
        if (is64) {
            const long long* p64 = (const long long*)ei;
            s = (int)p64[i];
            d = (int)p64[E + i];
        } else {
            s = p32[i];
            d = p32[E + i];
        }
        int pos = atomicAdd(&g_cursor[s], 1);
        g_dsts[pos] = d;
    }
}

// ---------------- GEMM: C[n,96] = A[n,96] @ W[96,96] + fused p/q ---------
// tile M=128, full N=96, K chunked by 32. 256 threads = 16x16, each thread
// computes an 8x6 microtile held as 8x3 packed f32x2 accumulators driven by
// fma.rn.f32x2. __launch_bounds__(256,3) caps regs at 85 so 3 CTAs/SM fit
// (R11 profile: 108 regs -> 2 CTAs/SM, occ 21.8%, issue 33.7% — latency
// bound; +50% warps is the fix).
__global__ __launch_bounds__(256, 3) void k_gemm(const float* __restrict__ Aext,
                                                 int useExt,
                                                 const float* __restrict__ W,
                                                 const float* __restrict__ av,
                                                 int n) {
    __shared__ float Xs[128 * 33];
    __shared__ float Ws[32 * 96];
    const float* A = useExt ? Aext : g_ha;

    int tx = threadIdx.x & 15;
    int ty = threadIdx.x >> 4;
    int rowBase = blockIdx.x * 128;

    unsigned long long acc2[8][3];
    #pragma unroll
    for (int r = 0; r < 8; r++)
        #pragma unroll
        for (int j = 0; j < 3; j++) acc2[r][j] = 0ull;

    for (int kc = 0; kc < 3; kc++) {
        for (int idx = threadIdx.x; idx < 128 * 8; idx += 256) {
            int r = idx >> 3, c4 = idx & 7;
            int gr = rowBase + r;
            float4 v = make_float4(0.f, 0.f, 0.f, 0.f);
            if (gr < n) v = *(const float4*)(A + gr * 96 + kc * 32 + c4 * 4);
            Xs[r * 33 + c4 * 4 + 0] = v.x;
            Xs[r * 33 + c4 * 4 + 1] = v.y;
            Xs[r * 33 + c4 * 4 + 2] = v.z;
            Xs[r * 33 + c4 * 4 + 3] = v.w;
        }
        for (int idx = threadIdx.x; idx < 32 * 24; idx += 256) {
            int r = idx / 24, c4 = idx - r * 24;
            *(float4*)(Ws + r * 96 + c4 * 4) =
                *(const float4*)(W + (kc * 32 + r) * 96 + c4 * 4);
        }
        __syncthreads();
        #pragma unroll 8
        for (int k = 0; k < 32; k++) {
            unsigned long long wv[3];
            const unsigned long long* wp =
                (const unsigned long long*)(Ws + k * 96 + tx * 6);
            wv[0] = wp[0]; wv[1] = wp[1]; wv[2] = wp[2];
            #pragma unroll
            for (int r = 0; r < 8; r++) {
                uint32_t xu = __float_as_uint(Xs[(ty * 8 + r) * 33 + k]);
                unsigned long long xx;
                BCAST_F32X2(xx, xu);
                FMA_F32X2(acc2[r][0], xx, wv[0]);
                FMA_F32X2(acc2[r][1], xx, wv[1]);
                FMA_F32X2(acc2[r][2], xx, wv[2]);
            }
        }
        __syncthreads();
    }

    float ap[6], aq[6];
    #pragma unroll
    for (int c = 0; c < 6; c++) {
        ap[c] = av[tx * 6 + c];
        aq[c] = av[96 + tx * 6 + c];
    }
    #pragma unroll
    for (int r = 0; r < 8; r++) {
        float acc[6];
        #pragma unroll
        for (int j = 0; j < 3; j++) {
            uint32_t lo, hi;
            UNPACK_F32X2(lo, hi, acc2[r][j]);
            acc[j * 2]     = __uint_as_float(lo);
            acc[j * 2 + 1] = __uint_as_float(hi);
        }
        int gr = rowBase + ty * 8 + r;
        float pl = 0.f, ql = 0.f;
        #pragma unroll
        for (int c = 0; c < 6; c++) {
            pl += acc[c] * ap[c];
            ql += acc[c] * aq[c];
        }
        #pragma unroll
        for (int o = 8; o; o >>= 1) {
            pl += __shfl_xor_sync(0xffffffffu, pl, o);
            ql += __shfl_xor_sync(0xffffffffu, ql, o);
        }
        if (gr < n) {
            #pragma unroll
            for (int c = 0; c < 6; c++)
                g_hg[gr * 96 + tx * 6 + c] = acc[c];
            if (tx == 0) { g_p[gr] = pl; g_q[gr] = ql; }
        }
    }
}

// ---------------- warp-per-node aggregation with fused edge weights ------
// avg degree = E/N = 8, so the deg<=32 single-chunk fast path is the common
// case: one weight computation, one broadcast loop, no chunk bookkeeping.
__global__ void k_agg(float* __restrict__ outExt, int useExt, int relu, int n) {
    int w = (blockIdx.x * blockDim.x + threadIdx.x) >> 5;
    int lane = threadIdx.x & 31;
    if (w >= n) return;
    float* out = useExt ? outExt : g_ha;
    int s = g_start[w];
    int deg = g_deg[w];
    float pw = g_p[w];
    float a0 = 0.f, a1 = 0.f, a2 = 0.f, sep = 0.f;

    if (deg <= 32) {
        int v = 0;
        float wt = 0.f;
        if (lane < deg) {
            v = __ldg(&g_dsts[s + lane]);
            float sc = pw + __ldg(&g_q[v]);
            float l = sc > 0.f ? sc : 0.01f * sc;
            wt = expf(-l);
        }
        sep = wt;
        for (int t = 0; t < deg; t++) {
            float w_t = __shfl_sync(0xffffffffu, wt, t);
            int   v_t = __shfl_sync(0xffffffffu, v, t);
            const float* hr = g_hg + v_t * 96;
            a0 += w_t * __ldg(hr + lane);
            a1 += w_t * __ldg(hr + lane + 32);
            a2 += w_t * __ldg(hr + lane + 64);
        }
    } else {
        int e0 = s + deg;
        for (int base = s; base < e0; base += 32) {
            int j = base + lane;
            int v = 0;
            float wt = 0.f;
            if (j < e0) {
                v = __ldg(&g_dsts[j]);
                float sc = pw + __ldg(&g_q[v]);
                float l = sc > 0.f ? sc : 0.01f * sc;
                wt = expf(-l);
            }
            sep += wt;
            int m = min(32, e0 - base);
            #pragma unroll 2
            for (int t = 0; t < m; t++) {
                float w_t = __shfl_sync(0xffffffffu, wt, t);
                int   v_t = __shfl_sync(0xffffffffu, v, t);
                const float* hr = g_hg + v_t * 96;
                a0 += w_t * __ldg(hr + lane);
                a1 += w_t * __ldg(hr + lane + 32);
                a2 += w_t * __ldg(hr + lane + 64);
            }
        }
    }
    #pragma unroll
    for (int o = 16; o; o >>= 1)
        sep += __shfl_xor_sync(0xffffffffu, sep, o);

    float inv = 1.0f / sep;
    a0 *= inv; a1 *= inv; a2 *= inv;
    if (relu) {
        a0 = fmaxf(a0, 0.f);
        a1 = fmaxf(a1, 0.f);
        a2 = fmaxf(a2, 0.f);
    }
    out[w * 96 + lane]      = a0;
    out[w * 96 + lane + 32] = a1;
    out[w * 96 + lane + 64] = a2;
}

// ---------------- launch -------------------------------------------------
// Structure build (deg/alloc/scatter) is independent of the layer-1 GEMM;
// fork it onto a side stream so the captured graph runs both concurrently.
extern "C" void kernel_launch(void* const* d_in, const int* in_sizes, int n_in,
                              void* d_out, int out_size) {
    const void*  ei = d_in[0];
    const float* x  = (const float*)d_in[1];
    const float* W1 = (const float*)d_in[2];
    const float* a1 = (const float*)d_in[3];
    const float* W2 = (const float*)d_in[4];
    const float* a2 = (const float*)d_in[5];
    float* out = (float*)d_out;

    int E = in_sizes[0] / 2;
    int n = in_sizes[1] / D;

    int eb = (E + 255) / 256;
    int nb = (n + 255) / 256;
    int gemmb = (n + 127) / 128;
    int warpb = (n * 32 + 255) / 256;

    static cudaStream_t s2 = nullptr;
    static cudaEvent_t evFork = nullptr, evJoin = nullptr;
    static int* p_deg = nullptr;
    static int* p_total = nullptr;
    if (s2 == nullptr) {
        cudaStreamCreateWithFlags(&s2, cudaStreamNonBlocking);
        cudaEventCreateWithFlags(&evFork, cudaEventDisableTiming);
        cudaEventCreateWithFlags(&evJoin, cudaEventDisableTiming);
        cudaGetSymbolAddress((void**)&p_deg, g_deg);
        cudaGetSymbolAddress((void**)&p_total, g_total);
    }

    // fork: structure chain on s2 (memset replaces the k_zero kernel)
    cudaEventRecord(evFork, 0);
    cudaStreamWaitEvent(s2, evFork, 0);
    cudaMemsetAsync(p_deg, 0, n * sizeof(int), s2);
    cudaMemsetAsync(p_total, 0, sizeof(int), s2);
    k_convert<<<eb, 256, 0, s2>>>(ei, E);
    k_alloc<<<nb, 256, 0, s2>>>(n);
    k_scatter<<<eb, 256, 0, s2>>>(ei, E);
    cudaEventRecord(evJoin, s2);

    // main stream: layer-1 GEMM runs concurrently with structure build
    k_gemm<<<gemmb, 256>>>(x, 1, W1, a1, n);

    // join, then the dependent chain
    cudaStreamWaitEvent(0, evJoin, 0);
    k_agg<<<warpb, 256>>>(out, 0, 0, n);             // -> g_ha
    k_gemm<<<gemmb, 256>>>(nullptr, 0, W2, a2, n);   // g_ha @ W2 -> g_hg
    k_agg<<<warpb, 256>>>(out, 1, 1, n);             // -> d_out with ReLU
}